// round 2
// baseline (speedup 1.0000x reference)
#include <cuda_runtime.h>

// GMM score, d=1. out[j] = (evals[j] - x[j]) / sigma2[j]
//   sigma2[j] = (exp(2*t*ln 25) - 1) / (2*ln 25)
//   pdf[i][j] = exp(-0.5*(tr[i]-x[j])^2 / sigma2[j])
//   evals[j]  = sum_i pdf*tr / sum_i pdf   (0 if denominator == 0)
//
// Design: one thread per query j. Train points staged in shared as {tr, tr*tr}
// so the exponent is 2 FFMAs:  a = k*tr^2 + (-2kx)*tr + k*x^2, with
// k = -1/(2*ln2*sigma2) so e = ex2.approx(a). Inner loop = 4 FMA-pipe ops +
// 1 MUFU -> both pipes bind at 8 cyc/warp-iter/SMSP.

#define TPB 128

__global__ __launch_bounds__(TPB, 1)
void gmm_score_kernel(const float* __restrict__ x,
                      const float* __restrict__ t,
                      const float* __restrict__ train,
                      float* __restrict__ out,
                      int B, int N)
{
    extern __shared__ float2 s_tr[];  // {tr, tr*tr}

    // Stage train points (broadcast-read later; each CTA reads 64KB from L2)
    for (int i = threadIdx.x; i < N; i += TPB) {
        float v = train[i];
        s_tr[i] = make_float2(v, v * v);
    }
    __syncthreads();

    int j = blockIdx.x * TPB + threadIdx.x;
    if (j >= B) return;

    const float xv = x[j];
    const float tv = t[j];

    const float LOG_S   = 3.2188758248682006f;   // ln(25)
    const float INV_LN2 = 1.4426950408889634f;
    float sigma2 = (expf(2.0f * tv * LOG_S) - 1.0f) / (2.0f * LOG_S);

    // k = -0.5/(sigma2) * (1/ln2)  so exp(-0.5 d^2/sigma2) = 2^(k*d^2)
    const float k  = -0.5f * INV_LN2 / sigma2;
    const float c1 = -2.0f * k * xv;   // coefficient of tr
    const float c0 = k * xv * xv;      // constant term

    float num = 0.0f;
    float den = 0.0f;

    #pragma unroll 16
    for (int i = 0; i < N; ++i) {
        float2 v = s_tr[i];                               // broadcast LDS.64
        float a = fmaf(k, v.y, fmaf(c1, v.x, c0));        // k*tr^2 + c1*tr + c0
        float e;
        asm("ex2.approx.ftz.f32 %0, %1;" : "=f"(e) : "f"(a));
        num = fmaf(e, v.x, num);
        den += e;
    }

    float evals = (den == 0.0f) ? 0.0f : (num / den);
    out[j] = (evals - xv) / sigma2;
}

extern "C" void kernel_launch(void* const* d_in, const int* in_sizes, int n_in,
                              void* d_out, int out_size)
{
    const float* x     = (const float*)d_in[0];
    const float* t     = (const float*)d_in[1];
    const float* train = (const float*)d_in[2];
    float* out = (float*)d_out;

    int B = in_sizes[0];   // 16384 queries
    int N = in_sizes[2];   // 16384 train points

    size_t smem = (size_t)N * sizeof(float2);   // 128 KB

    static int attr_done = 0;
    if (!attr_done) {
        cudaFuncSetAttribute(gmm_score_kernel,
                             cudaFuncAttributeMaxDynamicSharedMemorySize,
                             (int)smem);
        attr_done = 1;   // set before graph capture (first call is correctness run)
    }

    int grid = (B + TPB - 1) / TPB;
    gmm_score_kernel<<<grid, TPB, smem>>>(x, t, train, out, B, N);
}